// round 7
// baseline (speedup 1.0000x reference)
#include <cuda_runtime.h>
#include <cuda_bf16.h>
#include <cstdint>

#define N_NODES 50000
#define N_EDGES 600000
#define D 128
#define NT 16

// ---------------- scratch (static __device__, no allocs) ----------------
__device__ float g_x0[N_NODES * D];     // embedded node features
__device__ float g_h1[N_NODES * D];     // layer-1 output
__device__ float g_agg[N_NODES * D];    // mean-aggregated neighbor features
__device__ float g_p[N_NODES * NT];     // h1 @ W2lc
__device__ float g_W1lT[D * D];         // W1_l^T, tf32-rounded
__device__ float g_W1rT[D * D];         // W1_r^T, tf32-rounded
__device__ int   g_deg[50176];          // padded degree array (49*1024)
__device__ int   g_off[N_NODES];
__device__ int   g_cur[N_NODES];
__device__ int   g_csr[N_EDGES];
__device__ float g_W2lc[D * NT];
__device__ float g_W2rc[D * NT];
__device__ float g_bcp[NT];

// ================= helpers =================
__device__ __forceinline__ float tf32r(float x) {
    uint32_t u;
    asm("cvt.rna.tf32.f32 %0, %1;" : "=r"(u) : "f"(x));
    return __uint_as_float(u);
}
__device__ __forceinline__ void mma_tf32(float* d, uint32_t a0, uint32_t a1,
                                         uint32_t a2, uint32_t a3,
                                         uint32_t b0, uint32_t b1) {
    asm volatile("mma.sync.aligned.m16n8k8.row.col.f32.tf32.tf32.f32 "
                 "{%0,%1,%2,%3}, {%4,%5,%6,%7}, {%8,%9}, {%0,%1,%2,%3};"
                 : "+f"(d[0]), "+f"(d[1]), "+f"(d[2]), "+f"(d[3])
                 : "r"(a0), "r"(a1), "r"(a2), "r"(a3), "r"(b0), "r"(b1));
}

// ================= prep: zero deg + gather x0 + fold W2 + transpose W1 =================
__global__ __launch_bounds__(256) void k_prep(const int* __restrict__ entity,
                                              const float* __restrict__ emb,
                                              const float* __restrict__ W2l,
                                              const float* __restrict__ W2r,
                                              const float* __restrict__ b2,
                                              const float* __restrict__ Wc,
                                              const float* __restrict__ bc,
                                              const float* __restrict__ W1l,
                                              const float* __restrict__ W1r) {
    int b = blockIdx.x, tid = threadIdx.x;
    if (b < 6250) {
        int node = b * 8 + (tid >> 5), lane = tid & 31;
        if (node < N_NODES) {
            int e = entity[node];
            ((float4*)(g_x0 + (size_t)node * D))[lane] =
                ((const float4*)(emb + (size_t)e * D))[lane];
        }
    } else if (b == 6250) {
        __shared__ float sWc[D * NT];
        for (int i = tid; i < D * NT; i += 256) sWc[i] = Wc[i];
        __syncthreads();
        for (int m = 0; m < 2; m++) {
            const float* W = m ? W2r : W2l;
            float* out = m ? g_W2rc : g_W2lc;
            for (int o = tid; o < D * NT; o += 256) {
                int i = o >> 4, c = o & 15;
                float acc = 0.f;
                #pragma unroll 8
                for (int k = 0; k < D; k++) acc += W[i * D + k] * sWc[k * NT + c];
                out[o] = acc;
            }
        }
        if (tid < NT) {
            float acc = bc[tid];
            for (int k = 0; k < D; k++) acc += b2[k] * sWc[k * NT + tid];
            g_bcp[tid] = acc;
        }
    } else if (b == 6251 || b == 6252) {
        const float* W = (b == 6251) ? W1l : W1r;
        float* O = (b == 6251) ? g_W1lT : g_W1rT;
        __shared__ float tile[32][33];
        int r = tid >> 5, c = tid & 31;
        for (int bi = 0; bi < 4; bi++)
            for (int bj = 0; bj < 4; bj++) {
                #pragma unroll
                for (int rr = 0; rr < 4; rr++)
                    tile[r + rr * 8][c] = W[(bi * 32 + r + rr * 8) * D + bj * 32 + c];
                __syncthreads();
                #pragma unroll
                for (int rr = 0; rr < 4; rr++)
                    O[(bj * 32 + r + rr * 8) * D + bi * 32 + c] = tf32r(tile[c][r + rr * 8]);
                __syncthreads();
            }
    } else {
        int base = (b - 6253) * 1024 + tid * 4;
        *(int4*)(g_deg + base) = make_int4(0, 0, 0, 0);
    }
}

// ================= CSR build =================
__global__ void k_count(const int* __restrict__ dst) {
    int e = blockIdx.x * blockDim.x + threadIdx.x;
    if (e < N_EDGES) atomicAdd(&g_deg[dst[e]], 1);
}

// single-block full exclusive scan over 50176 padded entries
__global__ __launch_bounds__(1024) void k_scan1() {
    __shared__ int wsum[32];
    int t = threadIdx.x, lane = t & 31, w = t >> 5;
    int base = t * 49;
    int s = 0;
    #pragma unroll 7
    for (int i = 0; i < 49; i++) s += g_deg[base + i];
    int incl = s;
    #pragma unroll
    for (int o = 1; o < 32; o <<= 1) {
        int v = __shfl_up_sync(~0u, incl, o);
        if (lane >= o) incl += v;
    }
    if (lane == 31) wsum[w] = incl;
    __syncthreads();
    if (t < 32) {
        int v = wsum[t];
        int inc = v;
        #pragma unroll
        for (int o = 1; o < 32; o <<= 1) {
            int u = __shfl_up_sync(~0u, inc, o);
            if (t >= o) inc += u;
        }
        wsum[t] = inc - v;
    }
    __syncthreads();
    int run = incl - s + wsum[w];
    #pragma unroll 7
    for (int i = 0; i < 49; i++) {
        int j = base + i;
        int dg = g_deg[j];
        if (j < N_NODES) { g_off[j] = run; g_cur[j] = run; }
        run += dg;
    }
}

__global__ void k_fill(const int* __restrict__ src, const int* __restrict__ dst) {
    int e = blockIdx.x * blockDim.x + threadIdx.x;
    if (e < N_EDGES) {
        int p = atomicAdd(&g_cur[dst[e]], 1);
        g_csr[p] = src[e];
    }
}

// ================= mean aggregation of x0: warp per node =================
__global__ __launch_bounds__(256) void k_agg() {
    const float* __restrict__ X = g_x0;
    int warp = (blockIdx.x * blockDim.x + threadIdx.x) >> 5;
    int lane = threadIdx.x & 31;
    if (warp >= N_NODES) return;
    int start = g_off[warp];
    int d = g_deg[warp];
    float ax = 0.f, ay = 0.f, az = 0.f, aw = 0.f;
    int e = 0;
    for (; e + 4 <= d; e += 4) {
        int s0 = g_csr[start + e + 0];
        int s1 = g_csr[start + e + 1];
        int s2 = g_csr[start + e + 2];
        int s3 = g_csr[start + e + 3];
        float4 v0 = ((const float4*)(X + (size_t)s0 * D))[lane];
        float4 v1 = ((const float4*)(X + (size_t)s1 * D))[lane];
        float4 v2 = ((const float4*)(X + (size_t)s2 * D))[lane];
        float4 v3 = ((const float4*)(X + (size_t)s3 * D))[lane];
        ax += v0.x + v1.x + v2.x + v3.x;
        ay += v0.y + v1.y + v2.y + v3.y;
        az += v0.z + v1.z + v2.z + v3.z;
        aw += v0.w + v1.w + v2.w + v3.w;
    }
    for (; e < d; e++) {
        int s0 = g_csr[start + e];
        float4 v0 = ((const float4*)(X + (size_t)s0 * D))[lane];
        ax += v0.x; ay += v0.y; az += v0.z; aw += v0.w;
    }
    float inv = 1.0f / (float)max(d, 1);
    ((float4*)(g_agg + (size_t)warp * D))[lane] =
        make_float4(ax * inv, ay * inv, az * inv, aw * inv);
}

// ================= layer-1 GEMM via mma.sync tf32 =================
// h1 = relu(agg@W1l + x0@W1r + b1). CTA: 128 rows. Warp: 16 rows x 128 cols.
// sA [128][36] (rows x k-chunk), sB [128][36] (out-cols x k-chunk). Pad 36 ->
// bank = (4r+c) mod 32, conflict-free fragment loads.
__global__ __launch_bounds__(256) void k_gemm(const float* __restrict__ bias) {
    __shared__ float sA[128][36];
    __shared__ float sB[128][36];
    __shared__ float sBias[D];
    int tid = threadIdx.x, wid = tid >> 5, lane = tid & 31;
    int bm = blockIdx.x * 128;
    if (tid < D) sBias[tid] = bias[tid];

    float acc[16][4];
    #pragma unroll
    for (int t = 0; t < 16; t++)
        #pragma unroll
        for (int j = 0; j < 4; j++) acc[t][j] = 0.f;

    int lr = lane >> 2;      // 0..7
    int lc = lane & 3;       // 0..3

    for (int ch = 0; ch < 8; ch++) {
        const float* A  = (ch < 4) ? g_agg : g_x0;
        const float* Bt = (ch < 4) ? g_W1lT : g_W1rT;
        int k0f4 = (ch & 3) * 8;
        #pragma unroll
        for (int i = 0; i < 4; i++) {
            int idx = tid + i * 256;        // 0..1023
            int r = idx >> 3, q = idx & 7;  // 128 rows x 8 float4
            int row = bm + r;
            float4 v = make_float4(0.f, 0.f, 0.f, 0.f);
            if (row < N_NODES) v = ((const float4*)A)[(size_t)row * 32 + k0f4 + q];
            float4 u;
            u.x = tf32r(v.x); u.y = tf32r(v.y); u.z = tf32r(v.z); u.w = tf32r(v.w);
            *(float4*)&sA[r][q * 4] = u;
            *(float4*)&sB[r][q * 4] = ((const float4*)Bt)[r * 32 + k0f4 + q];  // pre-rounded
        }
        __syncthreads();
        const uint32_t* uA = (const uint32_t*)sA;
        const uint32_t* uB = (const uint32_t*)sB;
        int arow = wid * 16 + lr;
        #pragma unroll
        for (int ks = 0; ks < 4; ks++) {
            int ka = ks * 8;
            uint32_t a0 = uA[arow * 36 + ka + lc];
            uint32_t a1 = uA[(arow + 8) * 36 + ka + lc];
            uint32_t a2 = uA[arow * 36 + ka + lc + 4];
            uint32_t a3 = uA[(arow + 8) * 36 + ka + lc + 4];
            #pragma unroll
            for (int t = 0; t < 16; t++) {
                uint32_t b0 = uB[(t * 8 + lr) * 36 + ka + lc];
                uint32_t b1 = uB[(t * 8 + lr) * 36 + ka + lc + 4];
                mma_tf32(acc[t], a0, a1, a2, a3, b0, b1);
            }
        }
        __syncthreads();
    }

    // epilogue: bias + relu, write h1
    int row0 = bm + wid * 16 + lr;
    int row1 = row0 + 8;
    #pragma unroll
    for (int t = 0; t < 16; t++) {
        int c0 = t * 8 + lc * 2;
        float bx = sBias[c0], by = sBias[c0 + 1];
        if (row0 < N_NODES) {
            float2 o;
            o.x = fmaxf(acc[t][0] + bx, 0.f);
            o.y = fmaxf(acc[t][1] + by, 0.f);
            *(float2*)&g_h1[(size_t)row0 * D + c0] = o;
        }
        if (row1 < N_NODES) {
            float2 o;
            o.x = fmaxf(acc[t][2] + bx, 0.f);
            o.y = fmaxf(acc[t][3] + by, 0.f);
            *(float2*)&g_h1[(size_t)row1 * D + c0] = o;
        }
    }
}

// ================= p = h1 @ W2lc [N,16] =================
__global__ __launch_bounds__(256) void k_proj() {
    __shared__ float sWl[D * NT];
    for (int i = threadIdx.x; i < D * NT; i += 256) sWl[i] = g_W2lc[i];
    __syncthreads();
    int warp = threadIdx.x >> 5, lane = threadIdx.x & 31;
    int node = blockIdx.x * 16 + warp * 2 + (lane >> 4);
    int c = lane & 15;
    if (node >= N_NODES) return;
    const float4* h4 = (const float4*)(g_h1 + (size_t)node * D);
    float acc = 0.f;
    #pragma unroll 8
    for (int q = 0; q < 32; q++) {
        float4 hv = h4[q];
        int k = q * 4;
        acc += hv.x * sWl[(k + 0) * NT + c] + hv.y * sWl[(k + 1) * NT + c]
             + hv.z * sWl[(k + 2) * NT + c] + hv.w * sWl[(k + 3) * NT + c];
    }
    g_p[node * NT + c] = acc;
}

// ================= out = mean_nbr(p) + h1@W2rc + bcp =================
__global__ __launch_bounds__(256) void k_out(float* __restrict__ out) {
    __shared__ float sWr[D * NT];
    __shared__ float sb[NT];
    for (int i = threadIdx.x; i < D * NT; i += 256) sWr[i] = g_W2rc[i];
    if (threadIdx.x < NT) sb[threadIdx.x] = g_bcp[threadIdx.x];
    __syncthreads();
    int warp = threadIdx.x >> 5, lane = threadIdx.x & 31;
    int node = blockIdx.x * 16 + warp * 2 + (lane >> 4);
    int c = lane & 15;
    if (node >= N_NODES) return;

    const float4* h4 = (const float4*)(g_h1 + (size_t)node * D);
    float acc = sb[c];
    #pragma unroll 8
    for (int q = 0; q < 32; q++) {
        float4 hv = h4[q];
        int k = q * 4;
        acc += hv.x * sWr[(k + 0) * NT + c] + hv.y * sWr[(k + 1) * NT + c]
             + hv.z * sWr[(k + 2) * NT + c] + hv.w * sWr[(k + 3) * NT + c];
    }

    int start = g_off[node];
    int d = g_deg[node];
    float s = 0.f;
    int e = 0;
    for (; e + 4 <= d; e += 4) {
        int s0 = g_csr[start + e + 0];
        int s1 = g_csr[start + e + 1];
        int s2 = g_csr[start + e + 2];
        int s3 = g_csr[start + e + 3];
        s += g_p[s0 * NT + c] + g_p[s1 * NT + c] + g_p[s2 * NT + c] + g_p[s3 * NT + c];
    }
    for (; e < d; e++) s += g_p[g_csr[start + e] * NT + c];
    acc += s / (float)max(d, 1);
    out[node * NT + c] = acc;
}

// ================= launch =================
extern "C" void kernel_launch(void* const* d_in, const int* in_sizes, int n_in,
                              void* d_out, int out_size) {
    const int*   entity = (const int*)d_in[0];
    const int*   edge   = (const int*)d_in[1];
    const float* emb    = (const float*)d_in[2];
    const float* W1l    = (const float*)d_in[3];
    const float* b1     = (const float*)d_in[4];
    const float* W1r    = (const float*)d_in[5];
    const float* W2l    = (const float*)d_in[6];
    const float* b2     = (const float*)d_in[7];
    const float* W2r    = (const float*)d_in[8];
    const float* Wc     = (const float*)d_in[9];
    const float* bc     = (const float*)d_in[10];
    float* out = (float*)d_out;

    const int* src = edge;
    const int* dst = edge + N_EDGES;

    k_prep<<<6302, 256>>>(entity, emb, W2l, W2r, b2, Wc, bc, W1l, W1r);
    k_count<<<(N_EDGES + 255) / 256, 256>>>(dst);
    k_scan1<<<1, 1024>>>();
    k_fill<<<(N_EDGES + 255) / 256, 256>>>(src, dst);
    k_agg<<<(N_NODES * 32 + 255) / 256, 256>>>();
    k_gemm<<<(N_NODES + 127) / 128, 256>>>(b1);
    k_proj<<<(N_NODES + 15) / 16, 256>>>();
    k_out<<<(N_NODES + 15) / 16, 256>>>(out);
}